// round 12
// baseline (speedup 1.0000x reference)
#include <cuda_runtime.h>
#include <cstdint>

// ---------------------------------------------------------------------------
// RipsECC. B=4096 points in [0,1]^3, 64 bins, bin(d) = ceil(31.5*d) in [0,55].
// All C(4096,2)=8,386,560 pairs are edges. out = cumsum(+4096 at bin0 - hist).
//
// 64-WARPS/SM build: 296 blocks x 1024 threads, 2 CTAs/SM resident.
// smem/CTA = 48KB coords (3 SoA arrays, prescaled x31.5; subtract form is a
// pure sum of squares -> m >= 0 by construction) + 64KB u8 histogram
// ([8 regions][64 bins][32 lanes] words; warp quad shares a word, byte bank
// = warp&3; RMW forced to ld/st.shared.u8 via inline PTX -> race-free).
// Binning: MUFU.SQRT + magic ceil, index MASKED with &63 (bounded).
// Units: 64-row superblocks s (lane owns i0=64s+lane, i1=64s+32+lane);
// 4 diagonal 16-j chunks (predicated) + (252-4s) off-diag 16-j chunks;
// prefix(s) = 2s(129-s), NUNITS = 8320 over 296*32 = 9472 warp slots.
// Max 32 counts per u8 slot. Tail: proven g_part matrix + ticket (R2-R9).
// ---------------------------------------------------------------------------

#define NPTS      4096
#define NSTEPS    64
#define NTHREADS  1024
#define NBLOCKS   296
#define NUNITS    8320
#define NREGIONS  8
#define HIST_WORDS (NREGIONS * NSTEPS * 32)          // 16384 words = 64 KB
#define PTS_FLOATS (3 * NPTS)                        // 48 KB
#define SMEM_BYTES (PTS_FLOATS * 4 + HIST_WORDS * 4) // 114688 B
#define MAGIC     8388608.0f                         // 2^23

__device__ int      g_part[NBLOCKS][NSTEPS];
__device__ unsigned g_ticket = 0;

extern __shared__ float smemf[];

// Byte-granular histogram increment (forced LDS.U8/STS.U8; no word RMW).
__device__ __forceinline__ void hinc(unsigned saddr) {
    asm volatile(
        "{\n\t.reg .u16 v;\n\t"
        "ld.shared.u8 v, [%0];\n\t"
        "add.u16 v, v, 1;\n\t"
        "st.shared.u8 [%0], v;\n\t}"
        :: "r"(saddr));
}

// byte offset = (ceil(sqrt(m)) & 63) * 128; m = (31.5 d)^2 >= 0 always.
__device__ __forceinline__ unsigned bin_off(float dx, float dy, float dz) {
    float m = fmaf(dx, dx, fmaf(dy, dy, dz * dz));
    float d;
    asm("sqrt.approx.f32 %0, %1;" : "=f"(d) : "f"(m));   // MUFU.SQRT
    unsigned f = __float_as_uint(__fadd_ru(d, MAGIC));   // 0x4B000000 + t
    return (f & 63u) << 7;                               // bounded index
}

__global__ void __launch_bounds__(NTHREADS, 2)
rips_ecc_kernel(const float* __restrict__ x, float* __restrict__ out) {
    float*    co   = smemf;                        // [3][4096]: X | Y | Z
    unsigned* hist = (unsigned*)(smemf + PTS_FLOATS);

    const int tid = threadIdx.x;

    // Stage 4 points per thread (3x LDG.128 -> 3x STS.128), prescaled 31.5.
    {
        const float4* xv = (const float4*)x;       // 3072 float4
        float4 v0 = xv[3 * tid + 0];
        float4 v1 = xv[3 * tid + 1];
        float4 v2 = xv[3 * tid + 2];
        float4 X = make_float4(31.5f*v0.x, 31.5f*v0.w, 31.5f*v1.z, 31.5f*v2.y);
        float4 Y = make_float4(31.5f*v0.y, 31.5f*v1.x, 31.5f*v1.w, 31.5f*v2.z);
        float4 Z = make_float4(31.5f*v0.z, 31.5f*v1.y, 31.5f*v2.x, 31.5f*v2.w);
        *(float4*)(co + 4 * tid)            = X;
        *(float4*)(co + NPTS + 4 * tid)     = Y;
        *(float4*)(co + 2 * NPTS + 4 * tid) = Z;
    }
    #pragma unroll
    for (int i = 0; i < HIST_WORDS / 4 / NTHREADS; i++)
        ((uint4*)hist)[i * NTHREADS + tid] = make_uint4(0u, 0u, 0u, 0u);
    __syncthreads();

    const int warp = tid >> 5;   // 0..31
    const int lane = tid & 31;
    // u8 slot shared address: region = warp>>2 (8192B), byte = lane*4+(warp&3)
    const unsigned hbase = (unsigned)__cvta_generic_to_shared(hist) +
                           (unsigned)((warp >> 2) * 8192 + lane * 4 + (warp & 3));

    const int u = warp * NBLOCKS + blockIdx.x;     // [0, 9472)
    if (u < NUNITS) {
        // prefix(s) = 2s(129-s); invert with sqrt guess + fixup.
        int s = (int)(0.5f * (129.0f - sqrtf((float)(16641 - 2 * u))));
        s = max(0, min(63, s));
        while (s > 0  && 2 * s * (129 - s) > u) --s;
        while (s < 63 && 2 * (s + 1) * (128 - s) <= u) ++s;
        const int rem = u - 2 * s * (129 - s);     // [0, 256-4s)
        const int sb  = s << 6;

        const float xi0 = co[sb + lane];
        const float yi0 = co[NPTS + sb + lane];
        const float zi0 = co[2 * NPTS + sb + lane];
        const float xi1 = co[sb + 32 + lane];
        const float yi1 = co[NPTS + sb + 32 + lane];
        const float zi1 = co[2 * NPTS + sb + 32 + lane];

        if (rem < 4) {
            // Diagonal chunk: jrel = 16*rem + jj in [0,64); count j > i only.
            const int jr0 = rem << 4;
            #pragma unroll
            for (int jj = 0; jj < 16; jj++) {
                int jrel = jr0 + jj;
                int j = sb + jrel;
                float xj = co[j], yj = co[NPTS + j], zj = co[2 * NPTS + j];
                unsigned o0 = bin_off(xi0 - xj, yi0 - yj, zi0 - zj);
                unsigned o1 = bin_off(xi1 - xj, yi1 - yj, zi1 - zj);
                if (jrel > lane)      hinc(hbase + o0);
                if (jrel > lane + 32) hinc(hbase + o1);
            }
        } else {
            // Off-diagonal chunk: 16 j's past the superblock.
            const int j0 = sb + 64 + ((rem - 4) << 4);
            #pragma unroll 8
            for (int jj = 0; jj < 16; jj++) {
                int j = j0 + jj;
                float xj = co[j], yj = co[NPTS + j], zj = co[2 * NPTS + j];
                unsigned o0 = bin_off(xi0 - xj, yi0 - yj, zi0 - zj);
                unsigned o1 = bin_off(xi1 - xj, yi1 - yj, zi1 - zj);
                hinc(hbase + o0);
                hinc(hbase + o1);
            }
        }
    }
    __syncthreads();

    // Block reduction: warp w reduces bins {2w, 2w+1}; dp4a sums the 4
    // byte-banks per word across 8 regions; write per-block partials.
    #pragma unroll
    for (int bb = 0; bb < 2; bb++) {
        int bin = warp * 2 + bb;
        int sa = 0;
        #pragma unroll
        for (int r = 0; r < NREGIONS; r++)
            sa = __dp4a((int)hist[r * 2048 + (bin << 5) + lane], 0x01010101, sa);
        #pragma unroll
        for (int o = 16; o > 0; o >>= 1)
            sa += __shfl_down_sync(0xffffffffu, sa, o);
        if (lane == 0)
            g_part[blockIdx.x][bin] = sa;
    }
    __threadfence();
    __syncthreads();

    __shared__ int s_last;
    if (tid == 0)
        s_last = (atomicAdd(&g_ticket, 1u) == NBLOCKS - 1);
    __syncthreads();
    if (!s_last) return;
    __threadfence();

    // --- last block: reduce 296x64 partials, cumsum, write, reset ticket ---
    __shared__ int red[NSTEPS * 16];
    {
        int bin = tid & 63;
        int grp = tid >> 6;               // 0..15
        int sa = 0;
        for (int b2 = grp; b2 < NBLOCKS; b2 += 16)
            sa += g_part[b2][bin];
        red[bin * 16 + grp] = sa;
    }
    __syncthreads();
    __shared__ int ecc[NSTEPS];
    if (tid < NSTEPS) {
        int tot = 0;
        #pragma unroll
        for (int g = 0; g < 16; g++) tot += red[tid * 16 + g];
        ecc[tid] = (tid == 0 ? NPTS : 0) - tot;
    }
    __syncthreads();
    if (tid < 32) {
        int e0 = ecc[tid];
        int e1 = ecc[tid + 32];
        #pragma unroll
        for (int d = 1; d < 32; d <<= 1) {
            int t = __shfl_up_sync(0xffffffffu, e0, d);
            if (tid >= d) e0 += t;
        }
        int tot = __shfl_sync(0xffffffffu, e0, 31);
        #pragma unroll
        for (int d = 1; d < 32; d <<= 1) {
            int t = __shfl_up_sync(0xffffffffu, e1, d);
            if (tid >= d) e1 += t;
        }
        e1 += tot;
        out[tid]      = (float)e0;
        out[tid + 32] = (float)e1;
    }
    if (tid == 0) g_ticket = 0;   // self-reset for graph replay
}

extern "C" void kernel_launch(void* const* d_in, const int* in_sizes, int n_in,
                              void* d_out, int out_size) {
    (void)in_sizes; (void)n_in; (void)out_size;
    const float* x = (const float*)d_in[0];
    float* out = (float*)d_out;

    cudaFuncSetAttribute(rips_ecc_kernel,
                         cudaFuncAttributeMaxDynamicSharedMemorySize, SMEM_BYTES);

    rips_ecc_kernel<<<NBLOCKS, NTHREADS, SMEM_BYTES>>>(x, out);
}

// round 13
// speedup vs baseline: 1.0680x; 1.0680x over previous
#include <cuda_runtime.h>
#include <cstdint>

// ---------------------------------------------------------------------------
// RipsECC. B=4096 points in [0,1]^3, 64 bins, bin(d) = ceil(31.5*d) in [0,55].
// All C(4096,2)=8,386,560 pairs are edges. out = cumsum(+4096 at bin0 - hist).
//
// TRUE 64-warps/SM build: 296 blocks x 1024 threads, 2 CTAs/SM co-resident.
// smem/CTA = 106496 B: co2 (x,y prescaled 31.5) 32KB + coz 16KB + 56-bin u8
// histogram 57344 B ([8 regions][56 bins][32 lanes] words; warp quad shares
// a word, byte bank = warp&3 -> race-free byte RMW, max 32 counts/slot).
// (+1KB reserve, 8KB granularity: 114688 x 2 = 229376 <= 233472.)
// Units: 64-row superblocks s; lane owns i0 = 64s+lane, i1 = 64s+32+lane.
// 4 diagonal 16-j chunks (predicated j>i) + (252-4s) off-diag 16-j chunks;
// prefix(s) = 2s(129-s), NUNITS = 8320 over 296*32 = 9472 warp slots.
// Tail: proven per-block g_part matrix + ticket + last-block scan.
// ---------------------------------------------------------------------------

#define NPTS      4096
#define NSTEPS    64
#define NBINS     56
#define NTHREADS  1024
#define NBLOCKS   296
#define NUNITS    8320
#define NREGIONS  8
#define RSTRIDE   (NBINS * 32)                       // words per region: 1792
#define HIST_WORDS (NREGIONS * RSTRIDE)              // 14336 words = 57344 B
#define CO2_FLOATS (2 * NPTS)                        // 32 KB
#define COZ_FLOATS NPTS                              // 16 KB
#define SMEM_BYTES ((CO2_FLOATS + COZ_FLOATS) * 4 + HIST_WORDS * 4) // 106496
#define MAGIC     8388608.0f                         // 2^23

__device__ int      g_part[NBLOCKS][NSTEPS];
__device__ unsigned g_ticket = 0;

extern __shared__ float smemf[];

// byte offset = min(ceil(sqrt(m)) & 63, 55) * 128;  m = (31.5 d)^2 >= 0.
__device__ __forceinline__ unsigned bin_off(float dx, float dy, float dz) {
    float m = fmaf(dx, dx, fmaf(dy, dy, dz * dz));
    float d;
    asm("sqrt.approx.f32 %0, %1;" : "=f"(d) : "f"(m));   // MUFU.SQRT
    unsigned f = __float_as_uint(__fadd_ru(d, MAGIC));   // 0x4B000000 + t
    unsigned t = f & 63u;
    t = min(t, (unsigned)(NBINS - 1));                   // defensive clamp
    return t << 7;
}

__global__ void __launch_bounds__(NTHREADS, 2)
rips_ecc_kernel(const float* __restrict__ x, float* __restrict__ out) {
    float2*        co2  = (float2*)smemf;                   // [4096] (X,Y)
    float*         coz  = smemf + CO2_FLOATS;               // [4096] Z
    unsigned*      hist = (unsigned*)(coz + COZ_FLOATS);    // [8][56][32]
    unsigned char* h8   = (unsigned char*)hist;

    const int tid = threadIdx.x;

    // Stage 4 points per thread (3x LDG.128), prescaled by 31.5, SoA split.
    {
        const float4* xv = (const float4*)x;        // 3072 float4
        float4 v0 = xv[3 * tid + 0];
        float4 v1 = xv[3 * tid + 1];
        float4 v2 = xv[3 * tid + 2];
        // points: (v0.x,v0.y,v0.z)(v0.w,v1.x,v1.y)(v1.z,v1.w,v2.x)(v2.y,v2.z,v2.w)
        float4* c4 = (float4*)(co2 + 4 * tid);
        c4[0] = make_float4(31.5f*v0.x, 31.5f*v0.y, 31.5f*v0.w, 31.5f*v1.x);
        c4[1] = make_float4(31.5f*v1.z, 31.5f*v1.w, 31.5f*v2.y, 31.5f*v2.z);
        *(float4*)(coz + 4 * tid) =
            make_float4(31.5f*v0.z, 31.5f*v1.y, 31.5f*v2.x, 31.5f*v2.w);
    }
    for (int i = tid; i < HIST_WORDS / 4; i += NTHREADS)
        ((uint4*)hist)[i] = make_uint4(0u, 0u, 0u, 0u);
    __syncthreads();

    const int warp = tid >> 5;   // 0..31
    const int lane = tid & 31;
    // u8 slot: region = warp>>2 (7168 B each), byte = lane*4 + (warp&3).
    unsigned char* myh = h8 + (warp >> 2) * (RSTRIDE * 4) +
                         lane * 4 + (warp & 3);

    const int u = warp * NBLOCKS + blockIdx.x;      // [0, 9472)
    if (u < NUNITS) {
        // prefix(s) = 2s(129-s); invert with sqrt guess + fixup.
        int s = (int)(0.5f * (129.0f - sqrtf((float)(16641 - 2 * u))));
        s = max(0, min(63, s));
        while (s > 0  && 2 * s * (129 - s) > u) --s;
        while (s < 63 && 2 * (s + 1) * (128 - s) <= u) ++s;
        const int rem = u - 2 * s * (129 - s);      // [0, 256-4s)
        const int sb  = s << 6;

        const float2 pi0 = co2[sb + lane];
        const float2 pi1 = co2[sb + 32 + lane];
        const float  zi0 = coz[sb + lane];
        const float  zi1 = coz[sb + 32 + lane];

        if (rem < 4) {
            // Diagonal chunk: jrel = 16*rem + jj in [0,64); count j > i only.
            const int jr0 = rem << 4;
            #pragma unroll
            for (int jj = 0; jj < 16; jj++) {
                int jrel = jr0 + jj;
                float2 pj = co2[sb + jrel];
                float  zj = coz[sb + jrel];
                unsigned o0 = bin_off(pi0.x - pj.x, pi0.y - pj.y, zi0 - zj);
                unsigned o1 = bin_off(pi1.x - pj.x, pi1.y - pj.y, zi1 - zj);
                if (jrel > lane)      myh[o0] += (unsigned char)1;
                if (jrel > lane + 32) myh[o1] += (unsigned char)1;
            }
        } else {
            // Off-diagonal chunk: 16 j's past the superblock.
            const int j0 = sb + 64 + ((rem - 4) << 4);
            #pragma unroll
            for (int jj = 0; jj < 16; jj++) {
                float2 pj = co2[j0 + jj];
                float  zj = coz[j0 + jj];
                unsigned o0 = bin_off(pi0.x - pj.x, pi0.y - pj.y, zi0 - zj);
                unsigned o1 = bin_off(pi1.x - pj.x, pi1.y - pj.y, zi1 - zj);
                myh[o0] += (unsigned char)1;
                myh[o1] += (unsigned char)1;
            }
        }
    }
    __syncthreads();

    // Block reduction: warps 0..27 reduce bins {2w, 2w+1} (dp4a over the 4
    // byte-banks x 8 regions); warp 28 zero-fills bins 56..63.
    if (warp < 28) {
        #pragma unroll
        for (int bb = 0; bb < 2; bb++) {
            int bin = warp * 2 + bb;
            int sa = 0;
            #pragma unroll
            for (int r = 0; r < NREGIONS; r++)
                sa = __dp4a((int)hist[r * RSTRIDE + (bin << 5) + lane],
                            0x01010101, sa);
            #pragma unroll
            for (int o = 16; o > 0; o >>= 1)
                sa += __shfl_down_sync(0xffffffffu, sa, o);
            if (lane == 0)
                g_part[blockIdx.x][bin] = sa;
        }
    } else if (warp == 28 && lane < NSTEPS - NBINS) {
        g_part[blockIdx.x][NBINS + lane] = 0;
    }
    __threadfence();
    __syncthreads();

    __shared__ int s_last;
    if (tid == 0)
        s_last = (atomicAdd(&g_ticket, 1u) == NBLOCKS - 1);
    __syncthreads();
    if (!s_last) return;
    __threadfence();

    // --- last block: reduce 296x64 partials, cumsum, write, reset ticket ---
    __shared__ int red[NSTEPS * 16];
    {
        int bin = tid & 63;
        int grp = tid >> 6;               // 0..15
        int sa = 0;
        for (int b2 = grp; b2 < NBLOCKS; b2 += 16)
            sa += g_part[b2][bin];
        red[bin * 16 + grp] = sa;
    }
    __syncthreads();
    __shared__ int ecc[NSTEPS];
    if (tid < NSTEPS) {
        int tot = 0;
        #pragma unroll
        for (int g = 0; g < 16; g++) tot += red[tid * 16 + g];
        ecc[tid] = (tid == 0 ? NPTS : 0) - tot;
    }
    __syncthreads();
    if (tid < 32) {
        int e0 = ecc[tid];
        int e1 = ecc[tid + 32];
        #pragma unroll
        for (int d = 1; d < 32; d <<= 1) {
            int t = __shfl_up_sync(0xffffffffu, e0, d);
            if (tid >= d) e0 += t;
        }
        int tot = __shfl_sync(0xffffffffu, e0, 31);
        #pragma unroll
        for (int d = 1; d < 32; d <<= 1) {
            int t = __shfl_up_sync(0xffffffffu, e1, d);
            if (tid >= d) e1 += t;
        }
        e1 += tot;
        out[tid]      = (float)e0;
        out[tid + 32] = (float)e1;
    }
    if (tid == 0) g_ticket = 0;   // self-reset for graph replay
}

extern "C" void kernel_launch(void* const* d_in, const int* in_sizes, int n_in,
                              void* d_out, int out_size) {
    (void)in_sizes; (void)n_in; (void)out_size;
    const float* x = (const float*)d_in[0];
    float* out = (float*)d_out;

    cudaFuncSetAttribute(rips_ecc_kernel,
                         cudaFuncAttributeMaxDynamicSharedMemorySize, SMEM_BYTES);

    rips_ecc_kernel<<<NBLOCKS, NTHREADS, SMEM_BYTES>>>(x, out);
}

// round 15
// speedup vs baseline: 1.3390x; 1.2538x over previous
#include <cuda_runtime.h>
#include <cstdint>

// ---------------------------------------------------------------------------
// RipsECC. B=4096 points in [0,1]^3, 64 bins, bin(d) = ceil(31.5*d) in [0,55].
// All C(4096,2)=8,386,560 pairs are edges. out = cumsum(+4096 at bin0 - hist).
//
// Consolidated floor build: 148 blocks x 1024 threads, 1 CTA/SM.
//  * pts float4 prescaled x31.5 with packed norm (64KB smem):
//    m = (31.5 d)^2 = K_i + w_j - 2(Xi Xj + Yi Yj + Zi Zj)  (FADD + 3 FFMA).
//  * 4-i register blocking: 128-row superblocks s; lane owns i_q = 128s+32q+
//    lane (q=0..3). ONE broadcast LDS.128 per j serves 4 pairs.
//  * bin: MUFU.SQRT + F2I.RU (NaN -> 0; t bounded in [0,55]).
//  * u8 histogram 64KB: [8 regions][64 bins][32 lanes] u32 words; warp quad
//    shares a word, byte bank = warp&3 (race-free byte RMW; <=64 counts/slot).
//    ZEROED IN FULL: 4 x STS.128 per thread (R10/R11/R14 died by zeroing only
//    1/4 of it -- uninitialized counters, nondeterministic output).
//  * units: per sb s, 8 diagonal 16-j chunks (predicated j>i) + (248-8s)
//    off-diag 16-j chunks; prefix(s) = 4s(65-s), NUNITS = 4224 over 4736.
//  * tail: proven per-block g_part matrix + ticket + last-block scan.
// ---------------------------------------------------------------------------

#define NPTS      4096
#define NSTEPS    64
#define NTHREADS  1024
#define NBLOCKS   148
#define NUNITS    4224
#define NREGIONS  8
#define HIST_WORDS (NREGIONS * NSTEPS * 32)        // 16384 words = 64 KB
#define SMEM_BYTES (NPTS * 16 + HIST_WORDS * 4)    // 64KB + 64KB = 131072

__device__ int      g_part[NBLOCKS][NSTEPS];
__device__ unsigned g_ticket = 0;

extern __shared__ float4 smem4[];

// t = ceil(sqrt(m)) in [0,55]; F2I.RU(NaN) = 0 keeps the index bounded even
// if cancellation makes m slightly negative.
__device__ __forceinline__ int bin_t(float A, float B, float C, float Kw,
                                     float4 p) {
    float m = fmaf(A, p.x, fmaf(B, p.y, fmaf(C, p.z, Kw)));
    float d;
    asm("sqrt.approx.f32 %0, %1;" : "=f"(d) : "f"(m));   // MUFU.SQRT
    return __float2int_ru(d);
}

__global__ void __launch_bounds__(NTHREADS, 1)
rips_ecc_kernel(const float* __restrict__ x, float* __restrict__ out) {
    float4*        pts  = smem4;                       // [4096] x31.5 + norm
    unsigned*      hist = (unsigned*)(smem4 + NPTS);   // [8][64][32] words
    unsigned char* h8   = (unsigned char*)hist;

    const int tid = threadIdx.x;

    // Stage points: thread t computes points 4t..4t+3 from 3 LDG.128.
    {
        const float4* xv = (const float4*)x;           // 3072 float4
        float4 v0 = xv[3 * tid + 0];
        float4 v1 = xv[3 * tid + 1];
        float4 v2 = xv[3 * tid + 2];
        float px, py, pz;
        px = 31.5f * v0.x; py = 31.5f * v0.y; pz = 31.5f * v0.z;
        pts[4 * tid + 0] = make_float4(px, py, pz,
                                       fmaf(px, px, fmaf(py, py, pz * pz)));
        px = 31.5f * v0.w; py = 31.5f * v1.x; pz = 31.5f * v1.y;
        pts[4 * tid + 1] = make_float4(px, py, pz,
                                       fmaf(px, px, fmaf(py, py, pz * pz)));
        px = 31.5f * v1.z; py = 31.5f * v1.w; pz = 31.5f * v2.x;
        pts[4 * tid + 2] = make_float4(px, py, pz,
                                       fmaf(px, px, fmaf(py, py, pz * pz)));
        px = 31.5f * v2.y; py = 31.5f * v2.z; pz = 31.5f * v2.w;
        pts[4 * tid + 3] = make_float4(px, py, pz,
                                       fmaf(px, px, fmaf(py, py, pz * pz)));
    }
    // Zero the FULL 64KB histogram: 4096 uint4 = 4 x STS.128 per thread.
    {
        uint4* h4 = (uint4*)hist;
        #pragma unroll
        for (int i = 0; i < HIST_WORDS / 4 / NTHREADS; i++)   // 4 iterations
            h4[i * NTHREADS + tid] = make_uint4(0u, 0u, 0u, 0u);
    }
    __syncthreads();

    const int warp = tid >> 5;   // 0..31
    const int lane = tid & 31;
    // u8 slot: region = warp>>2 (8192 B each), byte = lane*4 + (warp&3).
    unsigned char* myh = h8 + (warp >> 2) * 8192 + lane * 4 + (warp & 3);

    const int u = warp * NBLOCKS + blockIdx.x;         // [0, 4736)
    if (u < NUNITS) {
        // prefix(s) = 4s(65-s); s = (65 - sqrt(4225-u))/2, fixup (R5-proven).
        int s = (int)(0.5f * (65.0f - sqrtf((float)(4225 - u))));
        s = max(0, min(31, s));
        while (s > 0  && 4 * s * (65 - s) > u) --s;
        while (s < 31 && 4 * (s + 1) * (64 - s) <= u) ++s;
        const int rem   = u - 4 * s * (65 - s);        // [0, 8*(32-s))
        const int sbase = s << 7;

        float4 q0 = pts[sbase + lane];
        float4 q1 = pts[sbase + 32 + lane];
        float4 q2 = pts[sbase + 64 + lane];
        float4 q3 = pts[sbase + 96 + lane];
        const float A0 = -2.0f*q0.x, B0 = -2.0f*q0.y, C0 = -2.0f*q0.z, K0 = q0.w;
        const float A1 = -2.0f*q1.x, B1 = -2.0f*q1.y, C1 = -2.0f*q1.z, K1 = q1.w;
        const float A2 = -2.0f*q2.x, B2 = -2.0f*q2.y, C2 = -2.0f*q2.z, K2 = q2.w;
        const float A3 = -2.0f*q3.x, B3 = -2.0f*q3.y, C3 = -2.0f*q3.z, K3 = q3.w;

        if (rem < 8) {
            // Diagonal chunk: jrel = 16*rem + jj; count (i_q, j) iff
            // jrel > 32q + lane.
            const int jr0 = rem << 4;
            #pragma unroll
            for (int jj = 0; jj < 16; jj++) {
                int jrel = jr0 + jj;
                float4 p = pts[sbase + jrel];
                int t0 = bin_t(A0, B0, C0, K0 + p.w, p);
                int t1 = bin_t(A1, B1, C1, K1 + p.w, p);
                int t2 = bin_t(A2, B2, C2, K2 + p.w, p);
                int t3 = bin_t(A3, B3, C3, K3 + p.w, p);
                if (jrel > lane)      myh[t0 << 7] += (unsigned char)1;
                if (jrel > lane + 32) myh[t1 << 7] += (unsigned char)1;
                if (jrel > lane + 64) myh[t2 << 7] += (unsigned char)1;
                if (jrel > lane + 96) myh[t3 << 7] += (unsigned char)1;
            }
        } else {
            // Off-diagonal chunk: 16 j's past the superblock.
            const int j0 = sbase + 128 + ((rem - 8) << 4);
            #pragma unroll
            for (int jj = 0; jj < 16; jj++) {
                float4 p = pts[j0 + jj];
                int t0 = bin_t(A0, B0, C0, K0 + p.w, p);
                int t1 = bin_t(A1, B1, C1, K1 + p.w, p);
                int t2 = bin_t(A2, B2, C2, K2 + p.w, p);
                int t3 = bin_t(A3, B3, C3, K3 + p.w, p);
                myh[t0 << 7] += (unsigned char)1;
                myh[t1 << 7] += (unsigned char)1;
                myh[t2 << 7] += (unsigned char)1;
                myh[t3 << 7] += (unsigned char)1;
            }
        }
    }
    __syncthreads();

    // Block reduction: warp w reduces bins {2w, 2w+1}; dp4a sums the 4
    // byte-banks per word across 8 regions; write per-block partials.
    #pragma unroll
    for (int bb = 0; bb < 2; bb++) {
        int bin = warp * 2 + bb;
        int sa = 0;
        #pragma unroll
        for (int r = 0; r < NREGIONS; r++)
            sa = __dp4a((int)hist[r * 2048 + (bin << 5) + lane], 0x01010101, sa);
        #pragma unroll
        for (int o = 16; o > 0; o >>= 1)
            sa += __shfl_down_sync(0xffffffffu, sa, o);
        if (lane == 0)
            g_part[blockIdx.x][bin] = sa;
    }
    __threadfence();
    __syncthreads();

    __shared__ int s_last;
    if (tid == 0)
        s_last = (atomicAdd(&g_ticket, 1u) == NBLOCKS - 1);
    __syncthreads();
    if (!s_last) return;
    __threadfence();

    // --- last block: reduce 148x64 partials, cumsum, write, reset ticket ---
    __shared__ int red[NSTEPS * 16];
    {
        int bin = tid & 63;
        int grp = tid >> 6;               // 0..15
        int sa = 0;
        for (int b2 = grp; b2 < NBLOCKS; b2 += 16)
            sa += g_part[b2][bin];
        red[bin * 16 + grp] = sa;
    }
    __syncthreads();
    __shared__ int ecc[NSTEPS];
    if (tid < NSTEPS) {
        int tot = 0;
        #pragma unroll
        for (int g = 0; g < 16; g++) tot += red[tid * 16 + g];
        ecc[tid] = (tid == 0 ? NPTS : 0) - tot;
    }
    __syncthreads();
    if (tid < 32) {
        int e0 = ecc[tid];
        int e1 = ecc[tid + 32];
        #pragma unroll
        for (int d = 1; d < 32; d <<= 1) {
            int t = __shfl_up_sync(0xffffffffu, e0, d);
            if (tid >= d) e0 += t;
        }
        int tot = __shfl_sync(0xffffffffu, e0, 31);
        #pragma unroll
        for (int d = 1; d < 32; d <<= 1) {
            int t = __shfl_up_sync(0xffffffffu, e1, d);
            if (tid >= d) e1 += t;
        }
        e1 += tot;
        out[tid]      = (float)e0;
        out[tid + 32] = (float)e1;
    }
    if (tid == 0) g_ticket = 0;   // self-reset for graph replay
}

extern "C" void kernel_launch(void* const* d_in, const int* in_sizes, int n_in,
                              void* d_out, int out_size) {
    (void)in_sizes; (void)n_in; (void)out_size;
    const float* x = (const float*)d_in[0];
    float* out = (float*)d_out;

    cudaFuncSetAttribute(rips_ecc_kernel,
                         cudaFuncAttributeMaxDynamicSharedMemorySize, SMEM_BYTES);

    rips_ecc_kernel<<<NBLOCKS, NTHREADS, SMEM_BYTES>>>(x, out);
}